// round 2
// baseline (speedup 1.0000x reference)
#include <cuda_runtime.h>
#include <math.h>

#define XF      1024
#define NB      2048
#define G       16
#define CHUNKS  32
#define ROWS_PER (NB / CHUNKS)   // 64

// scratch (no allocs allowed -> __device__ globals)
__device__ float g_partialA[CHUNKS * XF];
__device__ float g_partialS[CHUNKS * XF];
__device__ float g_partialSS[CHUNKS * XF];
__device__ float g_mean1[XF];
__device__ float g_scale[XF];
__device__ float g_shift[XF];

// Pass A1: partial column sums. grid (4, 32) x 256 threads. Coalesced: thread -> column.
__global__ void kA1(const float* __restrict__ xf) {
    int col = blockIdx.x * blockDim.x + threadIdx.x;
    int rc  = blockIdx.y;
    const float* p = xf + (size_t)rc * ROWS_PER * XF + col;
    float s0 = 0.f, s1 = 0.f, s2 = 0.f, s3 = 0.f;
    #pragma unroll
    for (int r = 0; r < ROWS_PER; r += 4) {
        s0 += p[(r + 0) * XF];
        s1 += p[(r + 1) * XF];
        s2 += p[(r + 2) * XF];
        s3 += p[(r + 3) * XF];
    }
    g_partialA[rc * XF + col] = (s0 + s1) + (s2 + s3);
}

// Pass A2: reduce partials -> mean1.  grid 4 x 256
__global__ void kA2() {
    int col = blockIdx.x * blockDim.x + threadIdx.x;
    float s = 0.f;
    #pragma unroll
    for (int c = 0; c < CHUNKS; c++) s += g_partialA[c * XF + col];
    g_mean1[col] = s * (1.0f / NB);
}

// Pass B1: partial sum & sumsq of relu(x - mean1). grid (4, 32) x 256
__global__ void kB1(const float* __restrict__ xf) {
    int col = blockIdx.x * blockDim.x + threadIdx.x;
    int rc  = blockIdx.y;
    float m = g_mean1[col];
    const float* p = xf + (size_t)rc * ROWS_PER * XF + col;
    float s = 0.f, ss = 0.f;
    #pragma unroll
    for (int r = 0; r < ROWS_PER; r++) {
        float v = p[r * XF] - m;
        v = fmaxf(v, 0.f);
        s  += v;
        ss += v * v;
    }
    g_partialS[rc * XF + col]  = s;
    g_partialSS[rc * XF + col] = ss;
}

// Pass B2: finalize stats -> scale/shift so pass C is one FMA. grid 4 x 256
__global__ void kB2(const float* __restrict__ wp) {
    int col = blockIdx.x * blockDim.x + threadIdx.x;
    float s = 0.f, ss = 0.f;
    #pragma unroll
    for (int c = 0; c < CHUNKS; c++) {
        s  += g_partialS[c * XF + col];
        ss += g_partialSS[c * XF + col];
    }
    float mu  = s * (1.0f / NB);
    float var = (ss - (float)NB * mu * mu) * (1.0f / (NB - 1));
    float sd  = sqrtf(var);
    float sc  = wp[0] / sd;
    g_scale[col] = sc;
    g_shift[col] = -mu * sc;
}

// Pass C: write pass. One block per row, 256 threads * float4 == 1024 cols.
// Each thread computes its 4 values once, writes G=16 coalesced float4 stores.
__global__ void __launch_bounds__(256) kC(const float* __restrict__ xf,
                                          float* __restrict__ out) {
    int row = blockIdx.x;
    int t   = threadIdx.x;

    float4 x  = reinterpret_cast<const float4*>(xf + (size_t)row * XF)[t];
    float4 m  = reinterpret_cast<const float4*>(g_mean1)[t];
    float4 sc = reinterpret_cast<const float4*>(g_scale)[t];
    float4 sh = reinterpret_cast<const float4*>(g_shift)[t];

    float4 v;
    v.x = fmaxf(x.x - m.x, 0.f) * sc.x + sh.x;
    v.y = fmaxf(x.y - m.y, 0.f) * sc.y + sh.y;
    v.z = fmaxf(x.z - m.z, 0.f) * sc.z + sh.z;
    v.w = fmaxf(x.w - m.w, 0.f) * sc.w + sh.w;

    float4* o = reinterpret_cast<float4*>(out + (size_t)row * XF * G) + t;
    #pragma unroll
    for (int g = 0; g < G; g++) {
        o[g * (XF / 4)] = v;
    }
}

extern "C" void kernel_launch(void* const* d_in, const int* in_sizes, int n_in,
                              void* d_out, int out_size) {
    const float* xf = (const float*)d_in[0];   // [2048, 1024] f32
    const float* wp = (const float*)d_in[1];   // [1] f32
    float* out = (float*)d_out;                // [2048, 16384] f32

    dim3 gridR(XF / 256, CHUNKS);
    kA1<<<gridR, 256>>>(xf);
    kA2<<<XF / 256, 256>>>();
    kB1<<<gridR, 256>>>(xf);
    kB2<<<XF / 256, 256>>>(wp);
    kC<<<NB, 256>>>(xf, out);
}

// round 5
// speedup vs baseline: 1.1800x; 1.1800x over previous
#include <cuda_runtime.h>
#include <math.h>

#define XF       1024
#define NB       2048
#define G        16
#define CHUNKS   32
#define ROWS_PER (NB / CHUNKS)   // 64
#define NBLOCKS  (CHUNKS * (XF / 256))  // 128 blocks in the reduction grids

// scratch (no allocs allowed -> __device__ globals)
__device__ float g_partialA[CHUNKS * XF];
__device__ float g_partialS[CHUNKS * XF];
__device__ float g_partialSS[CHUNKS * XF];
__device__ float g_mean1[XF];
__device__ float g_scale[XF];
__device__ float g_shift[XF];
__device__ unsigned int g_cnt1 = 0;
__device__ unsigned int g_cnt2 = 0;

// ──────────────────────────────────────────────────────────────────────────
// K1: partial column sums + last-block finalize -> g_mean1
// grid (4, 32) x 256 threads. Coalesced: thread -> column.
// ──────────────────────────────────────────────────────────────────────────
__global__ void __launch_bounds__(256) k_mean(const float* __restrict__ xf) {
    int col = blockIdx.x * blockDim.x + threadIdx.x;
    int rc  = blockIdx.y;
    const float* p = xf + (size_t)rc * ROWS_PER * XF + col;
    float s0 = 0.f, s1 = 0.f, s2 = 0.f, s3 = 0.f;
    #pragma unroll
    for (int r = 0; r < ROWS_PER; r += 4) {
        s0 += p[(r + 0) * XF];
        s1 += p[(r + 1) * XF];
        s2 += p[(r + 2) * XF];
        s3 += p[(r + 3) * XF];
    }
    g_partialA[rc * XF + col] = (s0 + s1) + (s2 + s3);

    // last-block finalize (threadFenceReduction pattern)
    __threadfence();
    __shared__ bool isLast;
    if (threadIdx.x == 0)
        isLast = (atomicAdd(&g_cnt1, 1u) == NBLOCKS - 1);
    __syncthreads();
    if (!isLast) return;

    #pragma unroll
    for (int cb = 0; cb < XF / 256; cb++) {
        int c = cb * 256 + threadIdx.x;
        float s = 0.f;
        #pragma unroll
        for (int k = 0; k < CHUNKS; k++) s += g_partialA[k * XF + c];
        g_mean1[c] = s * (1.0f / NB);
    }
    __threadfence();
    if (threadIdx.x == 0) g_cnt1 = 0;   // reset for next graph replay
}

// ──────────────────────────────────────────────────────────────────────────
// K2: partial sum/sumsq of relu(x - mean1) + last-block finalize
//     -> g_scale[f] = wp/sd,  g_shift[f] = -mu*wp/sd
// grid (4, 32) x 256 threads
// ──────────────────────────────────────────────────────────────────────────
__global__ void __launch_bounds__(256) k_stats(const float* __restrict__ xf,
                                               const float* __restrict__ wp) {
    int col = blockIdx.x * blockDim.x + threadIdx.x;
    int rc  = blockIdx.y;
    float m = g_mean1[col];
    const float* p = xf + (size_t)rc * ROWS_PER * XF + col;
    float s = 0.f, ss = 0.f;
    #pragma unroll
    for (int r = 0; r < ROWS_PER; r++) {
        float v = fmaxf(p[r * XF] - m, 0.f);
        s  += v;
        ss += v * v;
    }
    g_partialS[rc * XF + col]  = s;
    g_partialSS[rc * XF + col] = ss;

    __threadfence();
    __shared__ bool isLast;
    if (threadIdx.x == 0)
        isLast = (atomicAdd(&g_cnt2, 1u) == NBLOCKS - 1);
    __syncthreads();
    if (!isLast) return;

    float w = wp[0];
    #pragma unroll
    for (int cb = 0; cb < XF / 256; cb++) {
        int c = cb * 256 + threadIdx.x;
        float S = 0.f, SS = 0.f;
        #pragma unroll
        for (int k = 0; k < CHUNKS; k++) {
            S  += g_partialS[k * XF + c];
            SS += g_partialSS[k * XF + c];
        }
        float mu  = S * (1.0f / NB);
        float var = (SS - (float)NB * mu * mu) * (1.0f / (NB - 1));
        float sc  = w / sqrtf(var);
        g_scale[c] = sc;
        g_shift[c] = -mu * sc;
    }
    __threadfence();
    if (threadIdx.x == 0) g_cnt2 = 0;
}

// ──────────────────────────────────────────────────────────────────────────
// K3: write pass. One block per row, 256 threads * float4 == 1024 cols.
// Each thread computes its 4 values once, issues G=16 coalesced streaming
// float4 stores (output is write-once, 134 MB >> L2: bypass with .cs so the
// 8 MB xf input stays L2-resident across all three kernels).
// ──────────────────────────────────────────────────────────────────────────
__global__ void __launch_bounds__(256) kC(const float* __restrict__ xf,
                                          float* __restrict__ out) {
    int row = blockIdx.x;
    int t   = threadIdx.x;

    float4 x  = reinterpret_cast<const float4*>(xf + (size_t)row * XF)[t];
    float4 m  = reinterpret_cast<const float4*>(g_mean1)[t];
    float4 sc = reinterpret_cast<const float4*>(g_scale)[t];
    float4 sh = reinterpret_cast<const float4*>(g_shift)[t];

    float4 v;
    v.x = fmaxf(x.x - m.x, 0.f) * sc.x + sh.x;
    v.y = fmaxf(x.y - m.y, 0.f) * sc.y + sh.y;
    v.z = fmaxf(x.z - m.z, 0.f) * sc.z + sh.z;
    v.w = fmaxf(x.w - m.w, 0.f) * sc.w + sh.w;

    float4* o = reinterpret_cast<float4*>(out + (size_t)row * XF * G) + t;
    #pragma unroll
    for (int g = 0; g < G; g++) {
        __stcs(&o[g * (XF / 4)], v);
    }
}

extern "C" void kernel_launch(void* const* d_in, const int* in_sizes, int n_in,
                              void* d_out, int out_size) {
    const float* xf = (const float*)d_in[0];   // [2048, 1024] f32
    const float* wp = (const float*)d_in[1];   // [1] f32
    float* out = (float*)d_out;                // [2048, 16384] f32

    dim3 gridR(XF / 256, CHUNKS);
    k_mean <<<gridR, 256>>>(xf);
    k_stats<<<gridR, 256>>>(xf, wp);
    kC     <<<NB,    256>>>(xf, out);
}

// round 6
// speedup vs baseline: 1.3108x; 1.1108x over previous
#include <cuda_runtime.h>
#include <math.h>

#define XF      1024
#define NB      2048
#define G       16
#define GRID    128
#define T       512
#define RPB     (NB / GRID)     // 16 rows per block
#define C4      (XF / 4)        // 256 float4 columns
#define NCHUNK  (GRID * 2)      // 256 partial chunks (2 row-halves per block)

// scratch (no allocs -> __device__ globals; ~3 MB)
__device__ float4 g_pA [NCHUNK][C4];
__device__ float4 g_pS [NCHUNK][C4];
__device__ float4 g_pSS[NCHUNK][C4];
__device__ float4 g_mean4 [C4];
__device__ float4 g_scale4[C4];
__device__ float4 g_shift4[C4];
__device__ unsigned g_count = 0;   // barrier arrivals (self-resets each barrier)
__device__ unsigned g_gen   = 0;   // barrier generation (monotone; compared to snapshot only)

// Reusable grid-wide barrier (sense via generation snapshot). All GRID blocks
// are co-resident (GRID=128 <= 148 SMs, 1 block/SM) so spinning is safe.
__device__ __forceinline__ void grid_sync() {
    __syncthreads();
    if (threadIdx.x == 0) {
        __threadfence();                                   // publish this block's writes
        unsigned gen = atomicAdd(&g_gen, 0u);              // snapshot BEFORE arrival
        unsigned old = atomicAdd(&g_count, 1u);
        if (old == GRID - 1) {
            atomicExch(&g_count, 0u);                      // safe: all arrived, none spinning on count
            __threadfence();
            atomicAdd(&g_gen, 1u);                         // release
        } else {
            while (*(volatile unsigned*)&g_gen == gen) { } // spin on generation
        }
        __threadfence();                                   // acquire
    }
    __syncthreads();
}

__device__ __forceinline__ float4 relu_sub(float4 x, float4 m) {
    float4 v;
    v.x = fmaxf(x.x - m.x, 0.f);
    v.y = fmaxf(x.y - m.y, 0.f);
    v.z = fmaxf(x.z - m.z, 0.f);
    v.w = fmaxf(x.w - m.w, 0.f);
    return v;
}

__global__ void __launch_bounds__(T, 1) k_fused(const float* __restrict__ xf,
                                                const float* __restrict__ wp,
                                                float* __restrict__ out) {
    const int b  = blockIdx.x;
    const int t  = threadIdx.x;
    const int c4 = t & (C4 - 1);       // 0..255 float4 column
    const int h  = t >> 8;             // 0/1 row-half
    const int r0 = b * RPB + h * (RPB / 2);
    const float4* x4 = reinterpret_cast<const float4*>(xf);

    __shared__ float4 sA[T];
    __shared__ float4 sB[T];

    // ── Phase 1: per-block partial column sums (8 rows/thread, float4) ──
    {
        float4 a = make_float4(0.f, 0.f, 0.f, 0.f);
        #pragma unroll
        for (int i = 0; i < RPB / 2; i++) {
            float4 x = x4[(size_t)(r0 + i) * C4 + c4];
            a.x += x.x; a.y += x.y; a.z += x.z; a.w += x.w;
        }
        g_pA[b * 2 + h][c4] = a;
    }
    grid_sync();

    // ── Phase 1b: distributed mean finalize. Block b owns c4 ∈ {2b, 2b+1} ──
    {
        const int c4l  = t & 1;
        const int chnk = t >> 1;       // 0..255
        sA[t] = g_pA[chnk][2 * b + c4l];
        __syncthreads();
        #pragma unroll
        for (int s = NCHUNK / 2; s > 0; s >>= 1) {
            if (chnk < s) {
                float4 o = sA[(chnk + s) * 2 + c4l];
                sA[t].x += o.x; sA[t].y += o.y; sA[t].z += o.z; sA[t].w += o.w;
            }
            __syncthreads();
        }
        if (chnk == 0) {
            float4 m = sA[c4l];
            const float inv = 1.0f / NB;
            m.x *= inv; m.y *= inv; m.z *= inv; m.w *= inv;
            g_mean4[2 * b + c4l] = m;
        }
    }
    grid_sync();

    // ── Phase 2: partial sum / sumsq of relu(x - mean) (xf L1-hot) ──
    {
        const float4 m = g_mean4[c4];
        float4 s  = make_float4(0.f, 0.f, 0.f, 0.f);
        float4 ss = make_float4(0.f, 0.f, 0.f, 0.f);
        #pragma unroll
        for (int i = 0; i < RPB / 2; i++) {
            float4 v = relu_sub(x4[(size_t)(r0 + i) * C4 + c4], m);
            s.x += v.x;       s.y += v.y;       s.z += v.z;       s.w += v.w;
            ss.x += v.x*v.x;  ss.y += v.y*v.y;  ss.z += v.z*v.z;  ss.w += v.w*v.w;
        }
        g_pS [b * 2 + h][c4] = s;
        g_pSS[b * 2 + h][c4] = ss;
    }
    grid_sync();

    // ── Phase 2b: distributed stats finalize -> scale/shift ──
    {
        const int c4l  = t & 1;
        const int chnk = t >> 1;
        sA[t] = g_pS [chnk][2 * b + c4l];
        sB[t] = g_pSS[chnk][2 * b + c4l];
        __syncthreads();
        #pragma unroll
        for (int s = NCHUNK / 2; s > 0; s >>= 1) {
            if (chnk < s) {
                float4 oa = sA[(chnk + s) * 2 + c4l];
                float4 ob = sB[(chnk + s) * 2 + c4l];
                sA[t].x += oa.x; sA[t].y += oa.y; sA[t].z += oa.z; sA[t].w += oa.w;
                sB[t].x += ob.x; sB[t].y += ob.y; sB[t].z += ob.z; sB[t].w += ob.w;
            }
            __syncthreads();
        }
        if (chnk == 0) {
            float w = wp[0];
            float4 S = sA[c4l], SS = sB[c4l];
            float4 sc, sh;
            const float invN = 1.0f / NB, invN1 = 1.0f / (NB - 1);
            {
                float mu = S.x * invN;
                float var = (SS.x - (float)NB * mu * mu) * invN1;
                sc.x = w / sqrtf(var); sh.x = -mu * sc.x;
            }
            {
                float mu = S.y * invN;
                float var = (SS.y - (float)NB * mu * mu) * invN1;
                sc.y = w / sqrtf(var); sh.y = -mu * sc.y;
            }
            {
                float mu = S.z * invN;
                float var = (SS.z - (float)NB * mu * mu) * invN1;
                sc.z = w / sqrtf(var); sh.z = -mu * sc.z;
            }
            {
                float mu = S.w * invN;
                float var = (SS.w - (float)NB * mu * mu) * invN1;
                sc.w = w / sqrtf(var); sh.w = -mu * sc.w;
            }
            g_scale4[2 * b + c4l] = sc;
            g_shift4[2 * b + c4l] = sh;
        }
    }
    grid_sync();

    // ── Phase 3: write pass. Same rows (L1-hot), 16 streaming tiled stores ──
    {
        const float4 m  = g_mean4 [c4];
        const float4 sc = g_scale4[c4];
        const float4 sh = g_shift4[c4];
        #pragma unroll
        for (int i = 0; i < RPB / 2; i++) {
            const int r = r0 + i;
            float4 x = x4[(size_t)r * C4 + c4];
            float4 v;
            v.x = fmaxf(x.x - m.x, 0.f) * sc.x + sh.x;
            v.y = fmaxf(x.y - m.y, 0.f) * sc.y + sh.y;
            v.z = fmaxf(x.z - m.z, 0.f) * sc.z + sh.z;
            v.w = fmaxf(x.w - m.w, 0.f) * sc.w + sh.w;
            float4* o = reinterpret_cast<float4*>(out) + (size_t)r * (C4 * G) + c4;
            #pragma unroll
            for (int g = 0; g < G; g++) {
                __stcs(o + g * C4, v);
            }
        }
    }
}

extern "C" void kernel_launch(void* const* d_in, const int* in_sizes, int n_in,
                              void* d_out, int out_size) {
    const float* xf = (const float*)d_in[0];   // [2048, 1024] f32
    const float* wp = (const float*)d_in[1];   // [1] f32
    float* out = (float*)d_out;                // [2048, 16384] f32
    k_fused<<<GRID, T>>>(xf, wp, out);
}

// round 9
// speedup vs baseline: 1.6474x; 1.2568x over previous
#include <cuda_runtime.h>
#include <math.h>

#define XF      1024
#define NB      2048
#define G       16
#define C4      (XF / 4)        // 256 float4 columns per row

// stats kernel geometry: 128 blocks x 512 threads.
// Block b owns 8 columns = float4-cols {2b, 2b+1}. Thread t: c = t&1 (which
// float4-col), rg = t>>1 (row-group 0..255), rows rg*8..rg*8+7 in registers.
#define GS      128
#define TS      512
#define RPT     (NB / (TS / 2)) // 8 rows per thread

__device__ float4 g_mean4 [C4];
__device__ float4 g_scale4[C4];
__device__ float4 g_shift4[C4];

// ──────────────────────────────────────────────────────────────────────────
// K1: column-strip stats. No grid sync: each block owns its columns over the
// FULL batch. Data held in registers across both reduction phases.
// ──────────────────────────────────────────────────────────────────────────
__global__ void __launch_bounds__(TS, 1) k_stats(const float* __restrict__ xf,
                                                 const float* __restrict__ wp) {
    const int t    = threadIdx.x;
    const int c    = t & 1;            // which float4-col of this block's pair
    const int rg   = t >> 1;           // 0..255 row-group
    const int col4 = blockIdx.x * 2 + c;
    const float4* x4 = reinterpret_cast<const float4*>(xf);

    __shared__ float4 sA[TS];
    __shared__ float4 sB[TS];
    __shared__ float4 sMean[2];

    // Phase 1: load 8 rows (kept in registers), column partial sums
    float4 xv[RPT];
    float4 a = make_float4(0.f, 0.f, 0.f, 0.f);
    #pragma unroll
    for (int i = 0; i < RPT; i++) {
        xv[i] = x4[(size_t)(rg * RPT + i) * C4 + col4];
        a.x += xv[i].x; a.y += xv[i].y; a.z += xv[i].z; a.w += xv[i].w;
    }
    sA[t] = a;
    __syncthreads();

    // tree-reduce over rg (stride-2 layout: element = rg*2 + c)
    #pragma unroll
    for (int s = TS / 4; s > 0; s >>= 1) {
        if (rg < s) {
            float4 o = sA[(rg + s) * 2 + c];
            sA[t].x += o.x; sA[t].y += o.y; sA[t].z += o.z; sA[t].w += o.w;
        }
        __syncthreads();
    }
    if (rg == 0) {
        float4 m = sA[c];
        const float inv = 1.0f / NB;
        m.x *= inv; m.y *= inv; m.z *= inv; m.w *= inv;
        sMean[c] = m;
    }
    __syncthreads();
    const float4 m = sMean[c];

    // Phase 2: relu stats from registers (no memory re-read)
    float4 s  = make_float4(0.f, 0.f, 0.f, 0.f);
    float4 ss = make_float4(0.f, 0.f, 0.f, 0.f);
    #pragma unroll
    for (int i = 0; i < RPT; i++) {
        float4 v;
        v.x = fmaxf(xv[i].x - m.x, 0.f);
        v.y = fmaxf(xv[i].y - m.y, 0.f);
        v.z = fmaxf(xv[i].z - m.z, 0.f);
        v.w = fmaxf(xv[i].w - m.w, 0.f);
        s.x += v.x;       s.y += v.y;       s.z += v.z;       s.w += v.w;
        ss.x += v.x*v.x;  ss.y += v.y*v.y;  ss.z += v.z*v.z;  ss.w += v.w*v.w;
    }
    sA[t] = s;
    sB[t] = ss;
    __syncthreads();
    #pragma unroll
    for (int sN = TS / 4; sN > 0; sN >>= 1) {
        if (rg < sN) {
            float4 oa = sA[(rg + sN) * 2 + c];
            float4 ob = sB[(rg + sN) * 2 + c];
            sA[t].x += oa.x; sA[t].y += oa.y; sA[t].z += oa.z; sA[t].w += oa.w;
            sB[t].x += ob.x; sB[t].y += ob.y; sB[t].z += ob.z; sB[t].w += ob.w;
        }
        __syncthreads();
    }

    if (rg == 0) {
        const float w = wp[0];
        float4 S = sA[c], SS = sB[c];
        const float invN = 1.0f / NB, invN1 = 1.0f / (NB - 1);
        float4 sc, sh;
        {
            float mu = S.x * invN;
            float var = (SS.x - (float)NB * mu * mu) * invN1;
            sc.x = w / sqrtf(var); sh.x = -mu * sc.x;
        }
        {
            float mu = S.y * invN;
            float var = (SS.y - (float)NB * mu * mu) * invN1;
            sc.y = w / sqrtf(var); sh.y = -mu * sc.y;
        }
        {
            float mu = S.z * invN;
            float var = (SS.z - (float)NB * mu * mu) * invN1;
            sc.z = w / sqrtf(var); sh.z = -mu * sc.z;
        }
        {
            float mu = S.w * invN;
            float var = (SS.w - (float)NB * mu * mu) * invN1;
            sc.w = w / sqrtf(var); sh.w = -mu * sc.w;
        }
        g_mean4 [col4] = m;
        g_scale4[col4] = sc;
        g_shift4[col4] = sh;
    }
}

// ──────────────────────────────────────────────────────────────────────────
// K2: write pass at full occupancy. One block per row, 256 threads x float4
// == 1024 cols; each thread computes once, issues G=16 coalesced streaming
// float4 stores (write-once output bypasses L2; xf stays L2-hot from K1).
// ──────────────────────────────────────────────────────────────────────────
__global__ void __launch_bounds__(256) k_write(const float* __restrict__ xf,
                                               float* __restrict__ out) {
    const int row = blockIdx.x;
    const int t   = threadIdx.x;

    float4 x  = reinterpret_cast<const float4*>(xf + (size_t)row * XF)[t];
    float4 m  = g_mean4 [t];
    float4 sc = g_scale4[t];
    float4 sh = g_shift4[t];

    float4 v;
    v.x = fmaxf(x.x - m.x, 0.f) * sc.x + sh.x;
    v.y = fmaxf(x.y - m.y, 0.f) * sc.y + sh.y;
    v.z = fmaxf(x.z - m.z, 0.f) * sc.z + sh.z;
    v.w = fmaxf(x.w - m.w, 0.f) * sc.w + sh.w;

    float4* o = reinterpret_cast<float4*>(out + (size_t)row * XF * G) + t;
    #pragma unroll
    for (int g = 0; g < G; g++) {
        __stcs(o + g * C4, v);
    }
}

extern "C" void kernel_launch(void* const* d_in, const int* in_sizes, int n_in,
                              void* d_out, int out_size) {
    const float* xf = (const float*)d_in[0];   // [2048, 1024] f32
    const float* wp = (const float*)d_in[1];   // [1] f32
    float* out = (float*)d_out;                // [2048, 16384] f32

    k_stats<<<GS, TS>>>(xf, wp);
    k_write<<<NB, 256>>>(xf, out);
}